// round 16
// baseline (speedup 1.0000x reference)
#include <cuda_runtime.h>
#include <cuda_fp16.h>
#include <cstdint>

#define BB 2
#define LL 1024
#define DM 768
#define DI 1536
#define DS 16
#define DTR 48
#define XD 80            // DT_RANK + 2*D_STATE
#define NL 6
#define VOCAB_N 32000
#define DE 384
#define TOK (BB*LL)      // 2048
#define CH 32            // scan chunks
#define CLEN 32          // steps per chunk (LL/CH)
#define DTK 64           // padded K for dt projection (48 -> 64)
#define XSPLIT 16        // x_proj split-K
#define OSPLIT 3         // out_proj split-K
#define ISPLIT 2         // in_proj split-K (fp16 partials, summed in conv/scanC)
#define XZP (TOK*2*DI)   // elements per in_proj partial buffer

typedef __half fp16;

// ------------------------- scratch (no allocation allowed) -------------------
__device__ __align__(128) float g_hp0[TOK*DM];       // out_proj partial 0
__device__ __align__(128) float g_hp1[TOK*DM];
__device__ __align__(128) float g_hp2[TOK*DM];
__device__ __align__(128) float g_residual[TOK*DM];
__device__ __align__(128) float g_xdbl[TOK*XD];
__device__ __align__(128) float g_xdp[XSPLIT*TOK*XD];   // x_proj partials
__device__ __align__(128) float g_P[BB*DI*CH*DS];
__device__ __align__(128) float g_S[BB*DI*CH*DS];
__device__ __align__(128) float g_hin[BB*DI*CH*DS];
__device__ __align__(128) fp16  g_xz16[ISPLIT*XZP];     // in_proj fp16 partials
__device__ __align__(128) fp16  g_dt16[TOK*DI];
__device__ __align__(128) fp16  g_hs16[TOK*DM];
__device__ __align__(128) fp16  g_xc16[TOK*DI];
__device__ __align__(128) fp16  g_y16[TOK*DI];
__device__ __align__(128) fp16  g_xd16[TOK*DTK];
// persistent fp16 weights (converted once per call, at graph start)
__device__ __align__(128) fp16  g_win16[NL*2*DI*DM];
__device__ __align__(128) fp16  g_wxp16[NL*XD*DI];
__device__ __align__(128) fp16  g_wdt16[NL*DI*DTK];
__device__ __align__(128) fp16  g_wout16[NL*DM*DI];
__device__ __align__(128) fp16  g_wemb16[VOCAB_N*DE];

// ----------- fp32 -> fp16 conversions ----------------------------------------
__global__ void cvt_flat_kernel(const float* __restrict__ src, fp16* __restrict__ dst,
                                int total8)
{
    int i = blockIdx.x * blockDim.x + threadIdx.x;
    if (i >= total8) return;
    const float4* s = (const float4*)src + (size_t)i*2;
    float4 a = s[0], b = s[1];
    __half2 h0 = __floats2half2_rn(a.x, a.y);
    __half2 h1 = __floats2half2_rn(a.z, a.w);
    __half2 h2 = __floats2half2_rn(b.x, b.y);
    __half2 h3 = __floats2half2_rn(b.z, b.w);
    uint4 o;
    o.x = *reinterpret_cast<uint32_t*>(&h0);
    o.y = *reinterpret_cast<uint32_t*>(&h1);
    o.z = *reinterpret_cast<uint32_t*>(&h2);
    o.w = *reinterpret_cast<uint32_t*>(&h3);
    *((uint4*)dst + i) = o;
}
__global__ void cvt_pad_kernel(const float* __restrict__ src, int lda, int Kin, int Kout,
                               int total, fp16* __restrict__ dst)
{
    int idx = blockIdx.x * blockDim.x + threadIdx.x;
    if (idx >= total) return;
    int m = idx / Kout, k = idx - m*Kout;
    float v = (k < Kin) ? src[(size_t)m*lda + k] : 0.f;
    dst[(size_t)m*Kout + k] = __float2half(v);
}

// ---- sum x_proj partials -> xd fp32 ; also produce padded fp16 dt input -----
__global__ void sumxd_kernel(const float* __restrict__ xdp,
                             float* __restrict__ xd, fp16* __restrict__ xd16)
{
    int idx = blockIdx.x * blockDim.x + threadIdx.x;
    if (idx >= TOK*XD) return;
    int m = idx / XD, k = idx - m*XD;
    float s = 0.f;
#pragma unroll
    for (int p = 0; p < XSPLIT; p++) s += xdp[(size_t)p*TOK*XD + idx];
    xd[idx] = s;
    if (k < DTR)          xd16[(size_t)m*DTK + k] = __float2half(s);
    else if (k < DTR+16)  xd16[(size_t)m*DTK + k] = __float2half(0.f);
}

// ---- layer-0 fused embed + rmsnorm: res = concat-embed ; hs16 = norm --------
__global__ __launch_bounds__(256) void addnorm_embed_kernel(
    const int* __restrict__ ids, const int* __restrict__ pos,
    const float* __restrict__ emb, const float* __restrict__ pemb,
    float* __restrict__ res, const float* __restrict__ w, fp16* __restrict__ outs)
{
    int t = blockIdx.x;
    int id = ids[t], ps = pos[t];
    float* rp = res + (size_t)t*DM;
    float v[3];
    float ss = 0.f;
#pragma unroll
    for (int q = 0; q < 3; q++) {
        int i = threadIdx.x + q*256;
        float u = (i < DE) ? emb[(size_t)id*DE + i] : pemb[(size_t)ps*DE + (i-DE)];
        v[q] = u;
        ss += u*u;
    }
#pragma unroll
    for (int o = 16; o > 0; o >>= 1) ss += __shfl_xor_sync(0xffffffffu, ss, o);
    __shared__ float red[8];
    if ((threadIdx.x & 31) == 0) red[threadIdx.x >> 5] = ss;
    __syncthreads();
    float tot = 0.f;
#pragma unroll
    for (int q = 0; q < 8; q++) tot += red[q];
    float rstd = rsqrtf(tot * (1.f/(float)DM) + 1e-5f);
#pragma unroll
    for (int q = 0; q < 3; q++) {
        int i = threadIdx.x + q*256;
        rp[i] = v[q];
        outs[(size_t)t*DM + i] = __float2half(v[q] * rstd * w[i]);
    }
}

// ---- fused: res += sum(partials) ; hs16 = fp16(rmsnorm(res)*w) --------------
__global__ __launch_bounds__(256) void addnorm_kernel(
    const float* __restrict__ h0, const float* __restrict__ h1,
    const float* __restrict__ h2, float* __restrict__ res,
    const float* __restrict__ w, fp16* __restrict__ outs)
{
    int t = blockIdx.x;
    const float* hp0 = h0 + (size_t)t*DM;
    const float* hp1 = h1 + (size_t)t*DM;
    const float* hp2 = h2 + (size_t)t*DM;
    float* rp = res + (size_t)t*DM;
    float v[3];
    float ss = 0.f;
#pragma unroll
    for (int q = 0; q < 3; q++) {
        int i = threadIdx.x + q*256;
        v[q] = hp0[i] + hp1[i] + hp2[i] + rp[i];
        ss += v[q]*v[q];
    }
#pragma unroll
    for (int o = 16; o > 0; o >>= 1) ss += __shfl_xor_sync(0xffffffffu, ss, o);
    __shared__ float red[8];
    if ((threadIdx.x & 31) == 0) red[threadIdx.x >> 5] = ss;
    __syncthreads();
    float tot = 0.f;
#pragma unroll
    for (int q = 0; q < 8; q++) tot += red[q];
    float rstd = rsqrtf(tot * (1.f/(float)DM) + 1e-5f);
#pragma unroll
    for (int q = 0; q < 3; q++) {
        int i = threadIdx.x + q*256;
        rp[i] = v[q];
        outs[(size_t)t*DM + i] = __float2half(v[q] * rstd * w[i]);
    }
}

// ---- depthwise causal conv (width 4) over summed in_proj partials ----------
__global__ void conv_silu_kernel(const fp16* __restrict__ xz,
                                 const float* __restrict__ cw,
                                 const float* __restrict__ cb,
                                 fp16* __restrict__ outs)
{
    int idx = blockIdx.x * blockDim.x + threadIdx.x;
    if (idx >= TOK*DI) return;
    int d = idx % DI;
    int t = idx / DI;
    int l = t % LL;
    float acc = cb[d];
    const fp16* base = xz + (size_t)t*(2*DI) + d;
#pragma unroll
    for (int j = 0; j < 4; j++) {
        int ll = l - 3 + j;
        if (ll >= 0) {
            ptrdiff_t o = (ptrdiff_t)(j-3)*(2*DI);
            float xv = __half2float(base[o]) + __half2float(base[o + XZP]);
            acc += cw[d*4+j] * xv;
        }
    }
    float v = acc / (1.f + __expf(-acc));
    outs[idx] = __float2half(v);
}

// ---------------- chunked selective scan (register-state, fp16 inputs) -------
__device__ __forceinline__ void build_powers(float r, float* pw)
{
    pw[0] = r;
#pragma unroll
    for (int n = 1; n < DS; n++) {
        int m = n + 1;
        pw[n] = pw[m/2 - 1] * pw[(m - m/2) - 1];
    }
}

__global__ __launch_bounds__(256) void scanA_kernel(
    const fp16* __restrict__ xc, const fp16* __restrict__ dt,
    const float* __restrict__ xd, const float* __restrict__ A_log,
    float* __restrict__ Pv, float* __restrict__ Sv)
{
    int g = blockIdx.x * 256 + threadIdx.x;     // ((b*CH + c)*DI + d)
    int d = g % DI;
    int bc = g / DI;
    int c = bc % CH;
    int b = bc / CH;
    float A[DS];
    bool fast = true;
#pragma unroll
    for (int n = 0; n < DS; n++) A[n] = -__expf(A_log[d*DS + n]);
    float A1 = A[0];
#pragma unroll
    for (int n = 0; n < DS; n++)
        fast = fast && (fabsf(A[n] - (float)(n+1)*A1) <= 1e-4f*fabsf(A[n]));

    int l0 = c * CLEN;
    const fp16* xcb = xc + ((size_t)b*LL + l0)*DI + d;
    const fp16* dtb = dt + ((size_t)b*LL + l0)*DI + d;
    const float* xdb = xd + ((size_t)b*LL + l0)*XD + DTR;

    float h[DS];
#pragma unroll
    for (int n = 0; n < DS; n++) h[n] = 0.f;

    if (fast) {
        float rp = 1.f;
        for (int i = 0; i < CLEN; i++) {
            float xv  = __half2float(xcb[(size_t)i*DI]);
            float dtv = __half2float(dtb[(size_t)i*DI]);
            float Bv[DS];
#pragma unroll
            for (int q = 0; q < 4; q++)
                *(float4*)(Bv + q*4) = *(const float4*)(xdb + (size_t)i*XD + q*4);
            float w = dtv * xv;
            float r = __expf(dtv * A1);
            rp *= r;
            float pw[DS];
            build_powers(r, pw);
#pragma unroll
            for (int n = 0; n < DS; n++) h[n] = pw[n]*h[n] + w*Bv[n];
        }
        float pp[DS];
        build_powers(rp, pp);
#pragma unroll
        for (int q = 0; q < 4; q++) {
            *(float4*)&Pv[(size_t)g*DS + q*4] = *(float4*)(pp + q*4);
            *(float4*)&Sv[(size_t)g*DS + q*4] = *(float4*)(h + q*4);
        }
    } else {
        float P[DS];
#pragma unroll
        for (int n = 0; n < DS; n++) P[n] = 1.f;
        for (int i = 0; i < CLEN; i++) {
            float xv  = __half2float(xcb[(size_t)i*DI]);
            float dtv = __half2float(dtb[(size_t)i*DI]);
            float Bv[DS];
#pragma unroll
            for (int q = 0; q < 4; q++)
                *(float4*)(Bv + q*4) = *(const float4*)(xdb + (size_t)i*XD + q*4);
            float w = dtv * xv;
#pragma unroll
            for (int n = 0; n < DS; n++) {
                float dA = __expf(dtv * A[n]);
                P[n] *= dA;
                h[n] = dA*h[n] + w*Bv[n];
            }
        }
#pragma unroll
        for (int q = 0; q < 4; q++) {
            *(float4*)&Pv[(size_t)g*DS + q*4] = *(float4*)(P + q*4);
            *(float4*)&Sv[(size_t)g*DS + q*4] = *(float4*)(h + q*4);
        }
    }
}

__global__ void scanB_kernel(const float* __restrict__ Pv, const float* __restrict__ Sv,
                             float* __restrict__ hin)
{
    int g = blockIdx.x * blockDim.x + threadIdx.x;
    if (g >= BB*DI*DS) return;
    int n = g % DS;
    int pd = g / DS;
    int d = pd % DI;
    int b = pd / DI;
    float h = 0.f;
#pragma unroll
    for (int c = 0; c < CH; c++) {
        size_t idx = ((size_t)(b*CH + c)*DI + d)*DS + n;
        hin[idx] = h;
        h = Pv[idx]*h + Sv[idx];
    }
}

__global__ __launch_bounds__(256) void scanC_kernel(
    const fp16* __restrict__ xc, const fp16* __restrict__ dt,
    const float* __restrict__ xd, const fp16* __restrict__ xz,
    const float* __restrict__ A_log, const float* __restrict__ Dv,
    const float* __restrict__ hin, fp16* __restrict__ ys)
{
    int g = blockIdx.x * 256 + threadIdx.x;
    int d = g % DI;
    int bc = g / DI;
    int c = bc % CH;
    int b = bc / CH;
    float A[DS];
    bool fast = true;
#pragma unroll
    for (int n = 0; n < DS; n++) A[n] = -__expf(A_log[d*DS + n]);
    float A1 = A[0];
#pragma unroll
    for (int n = 0; n < DS; n++)
        fast = fast && (fabsf(A[n] - (float)(n+1)*A1) <= 1e-4f*fabsf(A[n]));
    float Dval = Dv[d];

    int l0 = c * CLEN;
    const fp16* xcb = xc + ((size_t)b*LL + l0)*DI + d;
    const fp16* dtb = dt + ((size_t)b*LL + l0)*DI + d;
    const float* xdb = xd + ((size_t)b*LL + l0)*XD + DTR;
    const fp16* xzb = xz + ((size_t)b*LL + l0)*(2*DI) + DI + d;
    fp16* yb = ys + ((size_t)b*LL + l0)*DI + d;

    float h[DS];
#pragma unroll
    for (int q = 0; q < 4; q++)
        *(float4*)(h + q*4) = *(const float4*)&hin[(size_t)g*DS + q*4];

    for (int i = 0; i < CLEN; i++) {
        float xv  = __half2float(xcb[(size_t)i*DI]);
        float dtv = __half2float(dtb[(size_t)i*DI]);
        float Bv[DS], Cv[DS];
#pragma unroll
        for (int q = 0; q < 4; q++) {
            *(float4*)(Bv + q*4) = *(const float4*)(xdb + (size_t)i*XD + q*4);
            *(float4*)(Cv + q*4) = *(const float4*)(xdb + (size_t)i*XD + DS + q*4);
        }
        float w = dtv * xv;
        float y = 0.f;
        if (fast) {
            float r = __expf(dtv * A1);
            float pw[DS];
            build_powers(r, pw);
#pragma unroll
            for (int n = 0; n < DS; n++) {
                h[n] = pw[n]*h[n] + w*Bv[n];
                y += h[n]*Cv[n];
            }
        } else {
#pragma unroll
            for (int n = 0; n < DS; n++) {
                float dA = __expf(dtv * A[n]);
                h[n] = dA*h[n] + w*Bv[n];
                y += h[n]*Cv[n];
            }
        }
        float z = __half2float(xzb[(size_t)i*(2*DI)])
                + __half2float(xzb[(size_t)i*(2*DI) + XZP]);
        float sig = 1.f / (1.f + __expf(-z));
        float v = (y + xv*Dval) * (z * sig);
        yb[(size_t)i*DI] = __float2half(v);
    }
}

// --------------------------- tensor-core GEMM (fp16) -------------------------
// ROUND-11 PROVEN CONFIG: 128x128 CTA, 8 warps (64x32 warp tile), BK=32,
// 4-stage cp.async pipeline, 256 threads, 2 CTAs/SM.
__device__ __forceinline__ void ldsm_x4(uint32_t* r, uint32_t addr){
    asm volatile("ldmatrix.sync.aligned.m8n8.x4.shared.b16 {%0,%1,%2,%3}, [%4];"
      : "=r"(r[0]),"=r"(r[1]),"=r"(r[2]),"=r"(r[3]) : "r"(addr));
}
__device__ __forceinline__ void mma_fp16(float* c, const uint32_t* a, const uint32_t* b){
    asm volatile("mma.sync.aligned.m16n8k16.row.col.f32.f16.f16.f32 "
      "{%0,%1,%2,%3}, {%4,%5,%6,%7}, {%8,%9}, {%0,%1,%2,%3};"
      : "+f"(c[0]),"+f"(c[1]),"+f"(c[2]),"+f"(c[3])
      : "r"(a[0]),"r"(a[1]),"r"(a[2]),"r"(a[3]), "r"(b[0]),"r"(b[1]));
}
__device__ __forceinline__ void cp16(uint32_t daddr, const void* gptr, uint32_t srcsz){
    asm volatile("cp.async.cg.shared.global [%0], [%1], 16, %2;\n"
      :: "r"(daddr), "l"(gptr), "r"(srcsz));
}

#define SSTRIDE 40
#define STAGE_ELEM (128*SSTRIDE)
#define STAGE_BYTES (STAGE_ELEM*2)
#define NSTAGE 4
#define GEMM_SMEM (NSTAGE*2*STAGE_BYTES)   // 81920 B

__global__ __launch_bounds__(256,2) void gemm_mma(
    const fp16* __restrict__ A, int lda, const fp16* __restrict__ B,
    void* __restrict__ Cv_, int N, int K2, int ldc,
    int mode, int pstride, int epi, const float* __restrict__ bias, int outhalf)
{
    extern __shared__ __align__(16) fp16 smem[];
    const int tid = threadIdx.x;
    const int lane = tid & 31, wid = tid >> 5;
    const int wm = wid & 1, wn = wid >> 1;
    const int bm = blockIdx.x * 128, bn = blockIdx.y * 128;

    const int ksplit = gridDim.z;
    const int per = (K2 / 32) / ksplit;
    const int kbeg = blockIdx.z * per * 32;
    const int iters = per;

    const int r0 = tid >> 2,            c0 = (tid & 3) * 8;
    const int r1 = (tid + 256) >> 2,    c1 = ((tid + 256) & 3) * 8;

    uint32_t sbase = (uint32_t)__cvta_generic_to_shared(smem);

    const int bw0 = bn + r0, bw1 = bn + r1;
    const bool bv0 = bw0 < N, bv1 = bw1 < N;
    const fp16* Bq0 = B + (size_t)(bv0 ? bw0 : 0)*K2;
    const fp16* Bq1 = B + (size_t)(bv1 ? bw1 : 0)*K2;
    const fp16* Aq0 = A + (size_t)(bm + r0)*lda;
    const fp16* Aq1 = A + (size_t)(bm + r1)*lda;

    const uint32_t aoff0 = (uint32_t)(r0*SSTRIDE + c0)*2;
    const uint32_t aoff1 = (uint32_t)(r1*SSTRIDE + c1)*2;

    float acc[4][4][4];
#pragma unroll
    for (int i = 0; i < 4; i++)
#pragma unroll
        for (int j = 0; j < 4; j++)
#pragma unroll
            for (int q = 0; q < 4; q++) acc[i][j][q] = 0.f;

#pragma unroll
    for (int s = 0; s < NSTAGE-1; s++) {
        if (s < iters) {
            int k = kbeg + s*32;
            uint32_t sA = sbase + (uint32_t)s*STAGE_BYTES;
            uint32_t sB = sbase + (uint32_t)(NSTAGE + s)*STAGE_BYTES;
            cp16(sA + aoff0, Aq0 + k + c0, 16u);
            cp16(sA + aoff1, Aq1 + k + c1, 16u);
            cp16(sB + aoff0, Bq0 + k + c0, bv0 ? 16u : 0u);
            cp16(sB + aoff1, Bq1 + k + c1, bv1 ? 16u : 0u);
        }
        asm volatile("cp.async.commit_group;\n" ::: "memory");
    }

    const int ar  = lane & 15;
    const int ak  = (lane >> 4) * 8;
    const int brr = (lane & 7) + ((lane >> 4) & 1)*8;
    const int bk  = ((lane >> 3) & 1) * 8;

    for (int it = 0; it < iters; it++) {
        int rem = iters - 1 - it;
        if (rem >= 2)      { asm volatile("cp.async.wait_group 2;\n" ::: "memory"); }
        else if (rem == 1) { asm volatile("cp.async.wait_group 1;\n" ::: "memory"); }
        else               { asm volatile("cp.async.wait_group 0;\n" ::: "memory"); }
        __syncthreads();

        {
            int s = it + NSTAGE - 1;
            if (s < iters) {
                int k = kbeg + s*32;
                int bufn = s & (NSTAGE-1);
                uint32_t sA = sbase + (uint32_t)bufn*STAGE_BYTES;
                uint32_t sB = sbase + (uint32_t)(NSTAGE + bufn)*STAGE_BYTES;
                cp16(sA + aoff0, Aq0 + k + c0, 16u);
                cp16(sA + aoff1, Aq1 + k + c1, 16u);
                cp16(sB + aoff0, Bq0 + k + c0, bv0 ? 16u : 0u);
                cp16(sB + aoff1, Bq1 + k + c1, bv1 ? 16u : 0u);
                asm volatile("cp.async.commit_group;\n" ::: "memory");
            }
        }

        int buf = it & (NSTAGE-1);
        uint32_t sAc = sbase + (uint32_t)buf*STAGE_BYTES;
        uint32_t sBc = sbase + (uint32_t)(NSTAGE + buf)*STAGE_BYTES;
#pragma unroll
        for (int kk = 0; kk < 2; kk++) {
            uint32_t afr[4][4], bfr[4][2];
#pragma unroll
            for (int mi = 0; mi < 4; mi++) {
                int row = wm*64 + mi*16 + ar;
                ldsm_x4(afr[mi], sAc + (uint32_t)(row*SSTRIDE + kk*16 + ak)*2);
            }
#pragma unroll
            for (int np = 0; np < 2; np++) {
                int row = wn*32 + np*16 + brr;
                uint32_t q4[4];
                ldsm_x4(q4, sBc + (uint32_t)(row*SSTRIDE + kk*16 + bk)*2);
                bfr[np*2+0][0]=q4[0]; bfr[np*2+0][1]=q4[1];
                bfr[np*2+1][0]=q4[2]; bfr[np*2+1][1]=q4[3];
            }
#pragma unroll
            for (int mi = 0; mi < 4; mi++)
#pragma unroll
                for (int ni = 0; ni < 4; ni++)
                    mma_fp16(acc[mi][ni], afr[mi], bfr[ni]);
        }
    }

    float* Cf = (float*)Cv_;
    fp16* Ch = (fp16*)Cv_;
    if (mode == 2) {
        Cf += (size_t)blockIdx.z * pstride;
        Ch += (size_t)blockIdx.z * pstride;
    }

    const int grp = lane >> 2, qd = lane & 3;
#pragma unroll
    for (int mi = 0; mi < 4; mi++) {
        int m = bm + wm*64 + mi*16 + grp;
#pragma unroll
        for (int ni = 0; ni < 4; ni++) {
            int n = bn + wn*32 + ni*8 + qd*2;
            if (n < N) {
                float c0v = acc[mi][ni][0], c1v = acc[mi][ni][1];
                float c2v = acc[mi][ni][2], c3v = acc[mi][ni][3];
                if (epi == 1) {
                    float b0 = bias[n], b1 = bias[n+1];
                    float x0 = c0v + b0, x1 = c1v + b1, x2 = c2v + b0, x3 = c3v + b1;
                    c0v = (x0 > 20.f) ? x0 : log1pf(__expf(x0));
                    c1v = (x1 > 20.f) ? x1 : log1pf(__expf(x1));
                    c2v = (x2 > 20.f) ? x2 : log1pf(__expf(x2));
                    c3v = (x3 > 20.f) ? x3 : log1pf(__expf(x3));
                }
                if (outhalf) {
                    *(__half2*)(&Ch[(size_t)m*ldc + n])     = __floats2half2_rn(c0v, c1v);
                    *(__half2*)(&Ch[(size_t)(m+8)*ldc + n]) = __floats2half2_rn(c2v, c3v);
                } else {
                    *(float2*)(&Cf[(size_t)m*ldc + n])     = make_float2(c0v, c1v);
                    *(float2*)(&Cf[(size_t)(m+8)*ldc + n]) = make_float2(c2v, c3v);
                }
            }
        }
    }
}

// ------------------------------- driver --------------------------------------
extern "C" void kernel_launch(void* const* d_in, const int* in_sizes, int n_in,
                              void* d_out, int out_size)
{
    (void)in_sizes; (void)n_in; (void)out_size;
    const int*   ids   = (const int*)d_in[0];
    const int*   pos   = (const int*)d_in[1];
    const float* emb   = (const float*)d_in[2];
    const float* pemb  = (const float*)d_in[3];
    const float* normw = (const float*)d_in[4];
    const float* inw   = (const float*)d_in[5];
    const float* convw = (const float*)d_in[6];
    const float* convb = (const float*)d_in[7];
    const float* xpw   = (const float*)d_in[8];
    const float* dtw   = (const float*)d_in[9];
    const float* dtb   = (const float*)d_in[10];
    const float* Alog  = (const float*)d_in[11];
    const float* Dvec  = (const float*)d_in[12];
    const float* outw  = (const float*)d_in[13];
    const float* normf = (const float*)d_in[14];
    float* logits = (float*)d_out;

    static int attr_done = 0;
    if (!attr_done) {
        cudaFuncSetAttribute(gemm_mma, cudaFuncAttributeMaxDynamicSharedMemorySize, GEMM_SMEM);
        attr_done = 1;
    }

    float *hp0, *hp1, *hp2, *res, *xd, *xdp, *Pv, *Sv, *hin;
    fp16 *xz16, *dt16, *hs16, *xc16, *y16, *xd16;
    fp16 *win16, *wxp16, *wdt16, *wout16, *wemb16;
    cudaGetSymbolAddress((void**)&hp0, g_hp0);
    cudaGetSymbolAddress((void**)&hp1, g_hp1);
    cudaGetSymbolAddress((void**)&hp2, g_hp2);
    cudaGetSymbolAddress((void**)&res, g_residual);
    cudaGetSymbolAddress((void**)&xd,  g_xdbl);
    cudaGetSymbolAddress((void**)&xdp, g_xdp);
    cudaGetSymbolAddress((void**)&Pv,  g_P);
    cudaGetSymbolAddress((void**)&Sv,  g_S);
    cudaGetSymbolAddress((void**)&hin, g_hin);
    cudaGetSymbolAddress((void**)&xz16, g_xz16);
    cudaGetSymbolAddress((void**)&dt16, g_dt16);
    cudaGetSymbolAddress((void**)&hs16, g_hs16);
    cudaGetSymbolAddress((void**)&xc16, g_xc16);
    cudaGetSymbolAddress((void**)&y16,  g_y16);
    cudaGetSymbolAddress((void**)&xd16, g_xd16);
    cudaGetSymbolAddress((void**)&win16,  g_win16);
    cudaGetSymbolAddress((void**)&wxp16,  g_wxp16);
    cudaGetSymbolAddress((void**)&wdt16,  g_wdt16);
    cudaGetSymbolAddress((void**)&wout16, g_wout16);
    cudaGetSymbolAddress((void**)&wemb16, g_wemb16);

    // -------- one-shot weight conversions (all layers, vectorized) --------
    cvt_flat_kernel<<<(NL*2*DI*DM/8 + 255)/256, 256>>>(inw, win16, NL*2*DI*DM/8);
    cvt_flat_kernel<<<(NL*XD*DI/8 + 255)/256, 256>>>(xpw, wxp16, NL*XD*DI/8);
    cvt_pad_kernel<<<(NL*DI*DTK + 255)/256, 256>>>(dtw, DTR, DTR, DTK, NL*DI*DTK, wdt16);
    cvt_flat_kernel<<<(NL*DM*DI/8 + 255)/256, 256>>>(outw, wout16, NL*DM*DI/8);
    cvt_flat_kernel<<<(VOCAB_N*DE/8 + 255)/256, 256>>>(emb, wemb16, VOCAB_N*DE/8);

    for (int layer = 0; layer < NL; layer++) {
        if (layer == 0) {
            // fused embed + rmsnorm (res initialized to embeddings)
            addnorm_embed_kernel<<<TOK, 256>>>(ids, pos, emb, pemb, res, normw, hs16);
        } else {
            addnorm_kernel<<<TOK, 256>>>(hp0, hp1, hp2, res,
                                         normw + (size_t)layer*DM, hs16);
        }

        // xz16 partials = fp16(hs @ in_proj^T) : N=3072, K=768, split-K=2
        { dim3 g(TOK/128, 2*DI/128, ISPLIT);
          gemm_mma<<<g, 256, GEMM_SMEM>>>(hs16, DM, win16 + (size_t)layer*2*DI*DM,
                                          xz16, 2*DI, DM, 2*DI, 2, XZP, 0, nullptr, 1); }

        conv_silu_kernel<<<(TOK*DI + 255)/256, 256>>>(
            xz16, convw + (size_t)layer*DI*4, convb + (size_t)layer*DI, xc16);

        // x_dbl partials: N=80, K=1536, split-K=16 -> 16 fp32 partial buffers
        { dim3 g(TOK/128, 1, XSPLIT);
          gemm_mma<<<g, 256, GEMM_SMEM>>>(xc16, DI, wxp16 + (size_t)layer*XD*DI,
                                          xdp, XD, DI, XD, 2, TOK*XD, 0, nullptr, 0); }
        sumxd_kernel<<<(TOK*XD + 255)/256, 256>>>(xdp, xd, xd16);

        // dt16 = fp16(softplus(x_dbl[:, :48] @ dt_proj^T + dtb)) : K padded 64
        { dim3 g(TOK/128, DI/128, 1);
          gemm_mma<<<g, 256, GEMM_SMEM>>>(xd16, DTK, wdt16 + (size_t)layer*DI*DTK,
                                          dt16, DI, DTK, DI, 0, 0, 1,
                                          dtb + (size_t)layer*DI, 1); }

        // chunked selective scan (register-state)
        scanA_kernel<<<(BB*CH*DI)/256, 256>>>(xc16, dt16, xd,
                                              Alog + (size_t)layer*DI*DS, Pv, Sv);
        scanB_kernel<<<(BB*DI*DS + 255)/256, 256>>>(Pv, Sv, hin);
        scanC_kernel<<<(BB*CH*DI)/256, 256>>>(xc16, dt16, xd, xz16,
                                              Alog + (size_t)layer*DI*DS,
                                              Dvec + (size_t)layer*DI, hin, y16);

        // out_proj partials: N=768, K=1536, split-K=3 -> hp0/hp1/hp2 (contiguous)
        { dim3 g(TOK/128, DM/128, OSPLIT);
          gemm_mma<<<g, 256, GEMM_SMEM>>>(y16, DI, wout16 + (size_t)layer*DM*DI,
                                          hp0, DM, DI, DM, 2, TOK*DM, 0, nullptr, 0); }
    }

    addnorm_kernel<<<TOK, 256>>>(hp0, hp1, hp2, res, normf, hs16);

    // logits = hs16[:, :384] @ emb^T : N=32000, K=384 (A stride = DM)
    { dim3 g(TOK/128, VOCAB_N/128, 1);
      gemm_mma<<<g, 256, GEMM_SMEM>>>(hs16, DM, wemb16, logits, VOCAB_N, DE, VOCAB_N,
                                      0, 0, 0, nullptr, 0); }
}

// round 17
// speedup vs baseline: 1.0552x; 1.0552x over previous
#include <cuda_runtime.h>
#include <cuda_fp16.h>
#include <cstdint>

#define BB 2
#define LL 1024
#define DM 768
#define DI 1536
#define DS 16
#define DTR 48
#define XD 80            // DT_RANK + 2*D_STATE
#define NL 6
#define VOCAB_N 32000
#define DE 384
#define TOK (BB*LL)      // 2048
#define CH 32            // scan chunks
#define CLEN 32          // steps per chunk (LL/CH)
#define DTK 64           // padded K for dt projection (48 -> 64)
#define XSPLIT 16        // x_proj split-K
#define OSPLIT 3         // out_proj split-K

typedef __half fp16;

// ------------------------- scratch (no allocation allowed) -------------------
__device__ __align__(128) float g_hp0[TOK*DM];       // out_proj partial 0
__device__ __align__(128) float g_hp1[TOK*DM];
__device__ __align__(128) float g_hp2[TOK*DM];
__device__ __align__(128) float g_residual[TOK*DM];
__device__ __align__(128) float g_xdbl[TOK*XD];
__device__ __align__(128) float g_xdp[XSPLIT*TOK*XD];   // x_proj partials
__device__ __align__(128) float g_P[BB*DI*CH*DS];
__device__ __align__(128) float g_S[BB*DI*CH*DS];
__device__ __align__(128) float g_hin[BB*DI*CH*DS];
__device__ __align__(128) fp16  g_xz16[TOK*2*DI];
__device__ __align__(128) fp16  g_dt16[TOK*DI];
__device__ __align__(128) fp16  g_hs16[TOK*DM];
__device__ __align__(128) fp16  g_xc16[TOK*DI];
__device__ __align__(128) fp16  g_y16[TOK*DI];
__device__ __align__(128) fp16  g_xd16[TOK*DTK];
// persistent fp16 weights (converted once per call, at graph start)
__device__ __align__(128) fp16  g_win16[NL*2*DI*DM];
__device__ __align__(128) fp16  g_wxp16[NL*XD*DI];
__device__ __align__(128) fp16  g_wdt16[NL*DI*DTK];
__device__ __align__(128) fp16  g_wout16[NL*DM*DI];
__device__ __align__(128) fp16  g_wemb16[VOCAB_N*DE];

// ----------- fp32 -> fp16 conversions ----------------------------------------
__global__ void cvt_flat_kernel(const float* __restrict__ src, fp16* __restrict__ dst,
                                int total8)
{
    int i = blockIdx.x * blockDim.x + threadIdx.x;
    if (i >= total8) return;
    const float4* s = (const float4*)src + (size_t)i*2;
    float4 a = s[0], b = s[1];
    __half2 h0 = __floats2half2_rn(a.x, a.y);
    __half2 h1 = __floats2half2_rn(a.z, a.w);
    __half2 h2 = __floats2half2_rn(b.x, b.y);
    __half2 h3 = __floats2half2_rn(b.z, b.w);
    uint4 o;
    o.x = *reinterpret_cast<uint32_t*>(&h0);
    o.y = *reinterpret_cast<uint32_t*>(&h1);
    o.z = *reinterpret_cast<uint32_t*>(&h2);
    o.w = *reinterpret_cast<uint32_t*>(&h3);
    *((uint4*)dst + i) = o;
}
__global__ void cvt_pad_kernel(const float* __restrict__ src, int lda, int Kin, int Kout,
                               int total, fp16* __restrict__ dst)
{
    int idx = blockIdx.x * blockDim.x + threadIdx.x;
    if (idx >= total) return;
    int m = idx / Kout, k = idx - m*Kout;
    float v = (k < Kin) ? src[(size_t)m*lda + k] : 0.f;
    dst[(size_t)m*Kout + k] = __float2half(v);
}

// ---- sum x_proj partials -> xd fp32 ; also produce padded fp16 dt input -----
__global__ void sumxd_kernel(const float* __restrict__ xdp,
                             float* __restrict__ xd, fp16* __restrict__ xd16)
{
    int idx = blockIdx.x * blockDim.x + threadIdx.x;
    if (idx >= TOK*XD) return;
    int m = idx / XD, k = idx - m*XD;
    float s = 0.f;
#pragma unroll
    for (int p = 0; p < XSPLIT; p++) s += xdp[(size_t)p*TOK*XD + idx];
    xd[idx] = s;
    if (k < DTR)          xd16[(size_t)m*DTK + k] = __float2half(s);
    else if (k < DTR+16)  xd16[(size_t)m*DTK + k] = __float2half(0.f);
}

// ---- layer-0 fused embed + rmsnorm: res = concat-embed ; hs16 = norm --------
__global__ __launch_bounds__(256) void addnorm_embed_kernel(
    const int* __restrict__ ids, const int* __restrict__ pos,
    const float* __restrict__ emb, const float* __restrict__ pemb,
    float* __restrict__ res, const float* __restrict__ w, fp16* __restrict__ outs)
{
    int t = blockIdx.x;
    int id = ids[t], ps = pos[t];
    float* rp = res + (size_t)t*DM;
    float v[3];
    float ss = 0.f;
#pragma unroll
    for (int q = 0; q < 3; q++) {
        int i = threadIdx.x + q*256;
        float u = (i < DE) ? emb[(size_t)id*DE + i] : pemb[(size_t)ps*DE + (i-DE)];
        v[q] = u;
        ss += u*u;
    }
#pragma unroll
    for (int o = 16; o > 0; o >>= 1) ss += __shfl_xor_sync(0xffffffffu, ss, o);
    __shared__ float red[8];
    if ((threadIdx.x & 31) == 0) red[threadIdx.x >> 5] = ss;
    __syncthreads();
    float tot = 0.f;
#pragma unroll
    for (int q = 0; q < 8; q++) tot += red[q];
    float rstd = rsqrtf(tot * (1.f/(float)DM) + 1e-5f);
#pragma unroll
    for (int q = 0; q < 3; q++) {
        int i = threadIdx.x + q*256;
        rp[i] = v[q];
        outs[(size_t)t*DM + i] = __float2half(v[q] * rstd * w[i]);
    }
}

// ---- fused: res += sum(partials) ; hs16 = fp16(rmsnorm(res)*w) --------------
__global__ __launch_bounds__(256) void addnorm_kernel(
    const float* __restrict__ h0, const float* __restrict__ h1,
    const float* __restrict__ h2, float* __restrict__ res,
    const float* __restrict__ w, fp16* __restrict__ outs)
{
    int t = blockIdx.x;
    const float* hp0 = h0 + (size_t)t*DM;
    const float* hp1 = h1 + (size_t)t*DM;
    const float* hp2 = h2 + (size_t)t*DM;
    float* rp = res + (size_t)t*DM;
    float v[3];
    float ss = 0.f;
#pragma unroll
    for (int q = 0; q < 3; q++) {
        int i = threadIdx.x + q*256;
        v[q] = hp0[i] + hp1[i] + hp2[i] + rp[i];
        ss += v[q]*v[q];
    }
#pragma unroll
    for (int o = 16; o > 0; o >>= 1) ss += __shfl_xor_sync(0xffffffffu, ss, o);
    __shared__ float red[8];
    if ((threadIdx.x & 31) == 0) red[threadIdx.x >> 5] = ss;
    __syncthreads();
    float tot = 0.f;
#pragma unroll
    for (int q = 0; q < 8; q++) tot += red[q];
    float rstd = rsqrtf(tot * (1.f/(float)DM) + 1e-5f);
#pragma unroll
    for (int q = 0; q < 3; q++) {
        int i = threadIdx.x + q*256;
        rp[i] = v[q];
        outs[(size_t)t*DM + i] = __float2half(v[q] * rstd * w[i]);
    }
}

// ---- depthwise causal conv (width 4, fp16 in) + bias + silu -> fp16 --------
__global__ void conv_silu_kernel(const fp16* __restrict__ xz,
                                 const float* __restrict__ cw,
                                 const float* __restrict__ cb,
                                 fp16* __restrict__ outs)
{
    int idx = blockIdx.x * blockDim.x + threadIdx.x;
    if (idx >= TOK*DI) return;
    int d = idx % DI;
    int t = idx / DI;
    int l = t % LL;
    float acc = cb[d];
    const fp16* base = xz + (size_t)t*(2*DI) + d;
#pragma unroll
    for (int j = 0; j < 4; j++) {
        int ll = l - 3 + j;
        if (ll >= 0) acc += cw[d*4+j] * __half2float(base[(ptrdiff_t)(j-3)*(2*DI)]);
    }
    float v = acc / (1.f + __expf(-acc));
    outs[idx] = __float2half(v);
}

// ---------------- chunked selective scan (register-state, fp16 inputs) -------
__device__ __forceinline__ void build_powers(float r, float* pw)
{
    pw[0] = r;
#pragma unroll
    for (int n = 1; n < DS; n++) {
        int m = n + 1;
        pw[n] = pw[m/2 - 1] * pw[(m - m/2) - 1];
    }
}

__global__ __launch_bounds__(256) void scanA_kernel(
    const fp16* __restrict__ xc, const fp16* __restrict__ dt,
    const float* __restrict__ xd, const float* __restrict__ A_log,
    float* __restrict__ Pv, float* __restrict__ Sv)
{
    int g = blockIdx.x * 256 + threadIdx.x;     // ((b*CH + c)*DI + d)
    int d = g % DI;
    int bc = g / DI;
    int c = bc % CH;
    int b = bc / CH;
    float A[DS];
    bool fast = true;
#pragma unroll
    for (int n = 0; n < DS; n++) A[n] = -__expf(A_log[d*DS + n]);
    float A1 = A[0];
#pragma unroll
    for (int n = 0; n < DS; n++)
        fast = fast && (fabsf(A[n] - (float)(n+1)*A1) <= 1e-4f*fabsf(A[n]));

    int l0 = c * CLEN;
    const fp16* xcb = xc + ((size_t)b*LL + l0)*DI + d;
    const fp16* dtb = dt + ((size_t)b*LL + l0)*DI + d;
    const float* xdb = xd + ((size_t)b*LL + l0)*XD + DTR;

    float h[DS];
#pragma unroll
    for (int n = 0; n < DS; n++) h[n] = 0.f;

    if (fast) {
        float rp = 1.f;
        for (int i = 0; i < CLEN; i++) {
            float xv  = __half2float(xcb[(size_t)i*DI]);
            float dtv = __half2float(dtb[(size_t)i*DI]);
            float Bv[DS];
#pragma unroll
            for (int q = 0; q < 4; q++)
                *(float4*)(Bv + q*4) = *(const float4*)(xdb + (size_t)i*XD + q*4);
            float w = dtv * xv;
            float r = __expf(dtv * A1);
            rp *= r;
            float pw[DS];
            build_powers(r, pw);
#pragma unroll
            for (int n = 0; n < DS; n++) h[n] = pw[n]*h[n] + w*Bv[n];
        }
        float pp[DS];
        build_powers(rp, pp);
#pragma unroll
        for (int q = 0; q < 4; q++) {
            *(float4*)&Pv[(size_t)g*DS + q*4] = *(float4*)(pp + q*4);
            *(float4*)&Sv[(size_t)g*DS + q*4] = *(float4*)(h + q*4);
        }
    } else {
        float P[DS];
#pragma unroll
        for (int n = 0; n < DS; n++) P[n] = 1.f;
        for (int i = 0; i < CLEN; i++) {
            float xv  = __half2float(xcb[(size_t)i*DI]);
            float dtv = __half2float(dtb[(size_t)i*DI]);
            float Bv[DS];
#pragma unroll
            for (int q = 0; q < 4; q++)
                *(float4*)(Bv + q*4) = *(const float4*)(xdb + (size_t)i*XD + q*4);
            float w = dtv * xv;
#pragma unroll
            for (int n = 0; n < DS; n++) {
                float dA = __expf(dtv * A[n]);
                P[n] *= dA;
                h[n] = dA*h[n] + w*Bv[n];
            }
        }
#pragma unroll
        for (int q = 0; q < 4; q++) {
            *(float4*)&Pv[(size_t)g*DS + q*4] = *(float4*)(P + q*4);
            *(float4*)&Sv[(size_t)g*DS + q*4] = *(float4*)(h + q*4);
        }
    }
}

__global__ void scanB_kernel(const float* __restrict__ Pv, const float* __restrict__ Sv,
                             float* __restrict__ hin)
{
    int g = blockIdx.x * blockDim.x + threadIdx.x;
    if (g >= BB*DI*DS) return;
    int n = g % DS;
    int pd = g / DS;
    int d = pd % DI;
    int b = pd / DI;
    float h = 0.f;
#pragma unroll
    for (int c = 0; c < CH; c++) {
        size_t idx = ((size_t)(b*CH + c)*DI + d)*DS + n;
        hin[idx] = h;
        h = Pv[idx]*h + Sv[idx];
    }
}

__global__ __launch_bounds__(256) void scanC_kernel(
    const fp16* __restrict__ xc, const fp16* __restrict__ dt,
    const float* __restrict__ xd, const fp16* __restrict__ xz,
    const float* __restrict__ A_log, const float* __restrict__ Dv,
    const float* __restrict__ hin, fp16* __restrict__ ys)
{
    int g = blockIdx.x * 256 + threadIdx.x;
    int d = g % DI;
    int bc = g / DI;
    int c = bc % CH;
    int b = bc / CH;
    float A[DS];
    bool fast = true;
#pragma unroll
    for (int n = 0; n < DS; n++) A[n] = -__expf(A_log[d*DS + n]);
    float A1 = A[0];
#pragma unroll
    for (int n = 0; n < DS; n++)
        fast = fast && (fabsf(A[n] - (float)(n+1)*A1) <= 1e-4f*fabsf(A[n]));
    float Dval = Dv[d];

    int l0 = c * CLEN;
    const fp16* xcb = xc + ((size_t)b*LL + l0)*DI + d;
    const fp16* dtb = dt + ((size_t)b*LL + l0)*DI + d;
    const float* xdb = xd + ((size_t)b*LL + l0)*XD + DTR;
    const fp16* xzb = xz + ((size_t)b*LL + l0)*(2*DI) + DI + d;
    fp16* yb = ys + ((size_t)b*LL + l0)*DI + d;

    float h[DS];
#pragma unroll
    for (int q = 0; q < 4; q++)
        *(float4*)(h + q*4) = *(const float4*)&hin[(size_t)g*DS + q*4];

    for (int i = 0; i < CLEN; i++) {
        float xv  = __half2float(xcb[(size_t)i*DI]);
        float dtv = __half2float(dtb[(size_t)i*DI]);
        float Bv[DS], Cv[DS];
#pragma unroll
        for (int q = 0; q < 4; q++) {
            *(float4*)(Bv + q*4) = *(const float4*)(xdb + (size_t)i*XD + q*4);
            *(float4*)(Cv + q*4) = *(const float4*)(xdb + (size_t)i*XD + DS + q*4);
        }
        float w = dtv * xv;
        float y = 0.f;
        if (fast) {
            float r = __expf(dtv * A1);
            float pw[DS];
            build_powers(r, pw);
#pragma unroll
            for (int n = 0; n < DS; n++) {
                h[n] = pw[n]*h[n] + w*Bv[n];
                y += h[n]*Cv[n];
            }
        } else {
#pragma unroll
            for (int n = 0; n < DS; n++) {
                float dA = __expf(dtv * A[n]);
                h[n] = dA*h[n] + w*Bv[n];
                y += h[n]*Cv[n];
            }
        }
        float z = __half2float(xzb[(size_t)i*(2*DI)]);
        float sig = 1.f / (1.f + __expf(-z));
        float v = (y + xv*Dval) * (z * sig);
        yb[(size_t)i*DI] = __float2half(v);
    }
}

// --------------------------- tensor-core GEMM (fp16) -------------------------
// ROUND-11 PROVEN CONFIG: 128x128 CTA, 8 warps (64x32 warp tile), BK=32,
// 4-stage cp.async pipeline, 256 threads, 2 CTAs/SM.
__device__ __forceinline__ void ldsm_x4(uint32_t* r, uint32_t addr){
    asm volatile("ldmatrix.sync.aligned.m8n8.x4.shared.b16 {%0,%1,%2,%3}, [%4];"
      : "=r"(r[0]),"=r"(r[1]),"=r"(r[2]),"=r"(r[3]) : "r"(addr));
}
__device__ __forceinline__ void mma_fp16(float* c, const uint32_t* a, const uint32_t* b){
    asm volatile("mma.sync.aligned.m16n8k16.row.col.f32.f16.f16.f32 "
      "{%0,%1,%2,%3}, {%4,%5,%6,%7}, {%8,%9}, {%0,%1,%2,%3};"
      : "+f"(c[0]),"+f"(c[1]),"+f"(c[2]),"+f"(c[3])
      : "r"(a[0]),"r"(a[1]),"r"(a[2]),"r"(a[3]), "r"(b[0]),"r"(b[1]));
}
__device__ __forceinline__ void cp16(uint32_t daddr, const void* gptr, uint32_t srcsz){
    asm volatile("cp.async.cg.shared.global [%0], [%1], 16, %2;\n"
      :: "r"(daddr), "l"(gptr), "r"(srcsz));
}

#define SSTRIDE 40
#define STAGE_ELEM (128*SSTRIDE)
#define STAGE_BYTES (STAGE_ELEM*2)
#define NSTAGE 4
#define GEMM_SMEM (NSTAGE*2*STAGE_BYTES)   // 81920 B

__global__ __launch_bounds__(256,2) void gemm_mma(
    const fp16* __restrict__ A, int lda, const fp16* __restrict__ B,
    void* __restrict__ Cv_, int N, int K2, int ldc,
    int mode, int pstride, int epi, const float* __restrict__ bias, int outhalf)
{
    extern __shared__ __align__(16) fp16 smem[];
    const int tid = threadIdx.x;
    const int lane = tid & 31, wid = tid >> 5;
    const int wm = wid & 1, wn = wid >> 1;
    const int bm = blockIdx.x * 128, bn = blockIdx.y * 128;

    const int ksplit = gridDim.z;
    const int per = (K2 / 32) / ksplit;
    const int kbeg = blockIdx.z * per * 32;
    const int iters = per;

    const int r0 = tid >> 2,            c0 = (tid & 3) * 8;
    const int r1 = (tid + 256) >> 2,    c1 = ((tid + 256) & 3) * 8;

    uint32_t sbase = (uint32_t)__cvta_generic_to_shared(smem);

    const int bw0 = bn + r0, bw1 = bn + r1;
    const bool bv0 = bw0 < N, bv1 = bw1 < N;
    const fp16* Bq0 = B + (size_t)(bv0 ? bw0 : 0)*K2;
    const fp16* Bq1 = B + (size_t)(bv1 ? bw1 : 0)*K2;
    const fp16* Aq0 = A + (size_t)(bm + r0)*lda;
    const fp16* Aq1 = A + (size_t)(bm + r1)*lda;

    const uint32_t aoff0 = (uint32_t)(r0*SSTRIDE + c0)*2;
    const uint32_t aoff1 = (uint32_t)(r1*SSTRIDE + c1)*2;

    float acc[4][4][4];
#pragma unroll
    for (int i = 0; i < 4; i++)
#pragma unroll
        for (int j = 0; j < 4; j++)
#pragma unroll
            for (int q = 0; q < 4; q++) acc[i][j][q] = 0.f;

#pragma unroll
    for (int s = 0; s < NSTAGE-1; s++) {
        if (s < iters) {
            int k = kbeg + s*32;
            uint32_t sA = sbase + (uint32_t)s*STAGE_BYTES;
            uint32_t sB = sbase + (uint32_t)(NSTAGE + s)*STAGE_BYTES;
            cp16(sA + aoff0, Aq0 + k + c0, 16u);
            cp16(sA + aoff1, Aq1 + k + c1, 16u);
            cp16(sB + aoff0, Bq0 + k + c0, bv0 ? 16u : 0u);
            cp16(sB + aoff1, Bq1 + k + c1, bv1 ? 16u : 0u);
        }
        asm volatile("cp.async.commit_group;\n" ::: "memory");
    }

    const int ar  = lane & 15;
    const int ak  = (lane >> 4) * 8;
    const int brr = (lane & 7) + ((lane >> 4) & 1)*8;
    const int bk  = ((lane >> 3) & 1) * 8;

    for (int it = 0; it < iters; it++) {
        int rem = iters - 1 - it;
        if (rem >= 2)      { asm volatile("cp.async.wait_group 2;\n" ::: "memory"); }
        else if (rem == 1) { asm volatile("cp.async.wait_group 1;\n" ::: "memory"); }
        else               { asm volatile("cp.async.wait_group 0;\n" ::: "memory"); }
        __syncthreads();

        {
            int s = it + NSTAGE - 1;
            if (s < iters) {
                int k = kbeg + s*32;
                int bufn = s & (NSTAGE-1);
                uint32_t sA = sbase + (uint32_t)bufn*STAGE_BYTES;
                uint32_t sB = sbase + (uint32_t)(NSTAGE + bufn)*STAGE_BYTES;
                cp16(sA + aoff0, Aq0 + k + c0, 16u);
                cp16(sA + aoff1, Aq1 + k + c1, 16u);
                cp16(sB + aoff0, Bq0 + k + c0, bv0 ? 16u : 0u);
                cp16(sB + aoff1, Bq1 + k + c1, bv1 ? 16u : 0u);
                asm volatile("cp.async.commit_group;\n" ::: "memory");
            }
        }

        int buf = it & (NSTAGE-1);
        uint32_t sAc = sbase + (uint32_t)buf*STAGE_BYTES;
        uint32_t sBc = sbase + (uint32_t)(NSTAGE + buf)*STAGE_BYTES;
#pragma unroll
        for (int kk = 0; kk < 2; kk++) {
            uint32_t afr[4][4], bfr[4][2];
#pragma unroll
            for (int mi = 0; mi < 4; mi++) {
                int row = wm*64 + mi*16 + ar;
                ldsm_x4(afr[mi], sAc + (uint32_t)(row*SSTRIDE + kk*16 + ak)*2);
            }
#pragma unroll
            for (int np = 0; np < 2; np++) {
                int row = wn*32 + np*16 + brr;
                uint32_t q4[4];
                ldsm_x4(q4, sBc + (uint32_t)(row*SSTRIDE + kk*16 + bk)*2);
                bfr[np*2+0][0]=q4[0]; bfr[np*2+0][1]=q4[1];
                bfr[np*2+1][0]=q4[2]; bfr[np*2+1][1]=q4[3];
            }
#pragma unroll
            for (int mi = 0; mi < 4; mi++)
#pragma unroll
                for (int ni = 0; ni < 4; ni++)
                    mma_fp16(acc[mi][ni], afr[mi], bfr[ni]);
        }
    }

    float* Cf = (float*)Cv_;
    if (mode == 2) Cf += (size_t)blockIdx.z * pstride;
    fp16* Ch = (fp16*)Cv_;

    const int grp = lane >> 2, qd = lane & 3;
#pragma unroll
    for (int mi = 0; mi < 4; mi++) {
        int m = bm + wm*64 + mi*16 + grp;
#pragma unroll
        for (int ni = 0; ni < 4; ni++) {
            int n = bn + wn*32 + ni*8 + qd*2;
            if (n < N) {
                float c0v = acc[mi][ni][0], c1v = acc[mi][ni][1];
                float c2v = acc[mi][ni][2], c3v = acc[mi][ni][3];
                if (epi == 1) {
                    float b0 = bias[n], b1 = bias[n+1];
                    float x0 = c0v + b0, x1 = c1v + b1, x2 = c2v + b0, x3 = c3v + b1;
                    c0v = (x0 > 20.f) ? x0 : log1pf(__expf(x0));
                    c1v = (x1 > 20.f) ? x1 : log1pf(__expf(x1));
                    c2v = (x2 > 20.f) ? x2 : log1pf(__expf(x2));
                    c3v = (x3 > 20.f) ? x3 : log1pf(__expf(x3));
                }
                if (outhalf) {
                    *(__half2*)(&Ch[(size_t)m*ldc + n])     = __floats2half2_rn(c0v, c1v);
                    *(__half2*)(&Ch[(size_t)(m+8)*ldc + n]) = __floats2half2_rn(c2v, c3v);
                } else {
                    *(float2*)(&Cf[(size_t)m*ldc + n])     = make_float2(c0v, c1v);
                    *(float2*)(&Cf[(size_t)(m+8)*ldc + n]) = make_float2(c2v, c3v);
                }
            }
        }
    }
}

// ------------------------------- driver --------------------------------------
extern "C" void kernel_launch(void* const* d_in, const int* in_sizes, int n_in,
                              void* d_out, int out_size)
{
    (void)in_sizes; (void)n_in; (void)out_size;
    const int*   ids   = (const int*)d_in[0];
    const int*   pos   = (const int*)d_in[1];
    const float* emb   = (const float*)d_in[2];
    const float* pemb  = (const float*)d_in[3];
    const float* normw = (const float*)d_in[4];
    const float* inw   = (const float*)d_in[5];
    const float* convw = (const float*)d_in[6];
    const float* convb = (const float*)d_in[7];
    const float* xpw   = (const float*)d_in[8];
    const float* dtw   = (const float*)d_in[9];
    const float* dtb   = (const float*)d_in[10];
    const float* Alog  = (const float*)d_in[11];
    const float* Dvec  = (const float*)d_in[12];
    const float* outw  = (const float*)d_in[13];
    const float* normf = (const float*)d_in[14];
    float* logits = (float*)d_out;

    static int attr_done = 0;
    if (!attr_done) {
        cudaFuncSetAttribute(gemm_mma, cudaFuncAttributeMaxDynamicSharedMemorySize, GEMM_SMEM);
        attr_done = 1;
    }

    float *hp0, *hp1, *hp2, *res, *xd, *xdp, *Pv, *Sv, *hin;
    fp16 *xz16, *dt16, *hs16, *xc16, *y16, *xd16;
    fp16 *win16, *wxp16, *wdt16, *wout16, *wemb16;
    cudaGetSymbolAddress((void**)&hp0, g_hp0);
    cudaGetSymbolAddress((void**)&hp1, g_hp1);
    cudaGetSymbolAddress((void**)&hp2, g_hp2);
    cudaGetSymbolAddress((void**)&res, g_residual);
    cudaGetSymbolAddress((void**)&xd,  g_xdbl);
    cudaGetSymbolAddress((void**)&xdp, g_xdp);
    cudaGetSymbolAddress((void**)&Pv,  g_P);
    cudaGetSymbolAddress((void**)&Sv,  g_S);
    cudaGetSymbolAddress((void**)&hin, g_hin);
    cudaGetSymbolAddress((void**)&xz16, g_xz16);
    cudaGetSymbolAddress((void**)&dt16, g_dt16);
    cudaGetSymbolAddress((void**)&hs16, g_hs16);
    cudaGetSymbolAddress((void**)&xc16, g_xc16);
    cudaGetSymbolAddress((void**)&y16,  g_y16);
    cudaGetSymbolAddress((void**)&xd16, g_xd16);
    cudaGetSymbolAddress((void**)&win16,  g_win16);
    cudaGetSymbolAddress((void**)&wxp16,  g_wxp16);
    cudaGetSymbolAddress((void**)&wdt16,  g_wdt16);
    cudaGetSymbolAddress((void**)&wout16, g_wout16);
    cudaGetSymbolAddress((void**)&wemb16, g_wemb16);

    // -------- one-shot weight conversions (all layers, vectorized) --------
    cvt_flat_kernel<<<(NL*2*DI*DM/8 + 255)/256, 256>>>(inw, win16, NL*2*DI*DM/8);
    cvt_flat_kernel<<<(NL*XD*DI/8 + 255)/256, 256>>>(xpw, wxp16, NL*XD*DI/8);
    cvt_pad_kernel<<<(NL*DI*DTK + 255)/256, 256>>>(dtw, DTR, DTR, DTK, NL*DI*DTK, wdt16);
    cvt_flat_kernel<<<(NL*DM*DI/8 + 255)/256, 256>>>(outw, wout16, NL*DM*DI/8);
    cvt_flat_kernel<<<(VOCAB_N*DE/8 + 255)/256, 256>>>(emb, wemb16, VOCAB_N*DE/8);

    for (int layer = 0; layer < NL; layer++) {
        if (layer == 0) {
            // fused embed + rmsnorm (res initialized to embeddings)
            addnorm_embed_kernel<<<TOK, 256>>>(ids, pos, emb, pemb, res, normw, hs16);
        } else {
            addnorm_kernel<<<TOK, 256>>>(hp0, hp1, hp2, res,
                                         normw + (size_t)layer*DM, hs16);
        }

        // xz16 = fp16(hs @ in_proj^T) : N=3072, K=768
        { dim3 g(TOK/128, 2*DI/128, 1);
          gemm_mma<<<g, 256, GEMM_SMEM>>>(hs16, DM, win16 + (size_t)layer*2*DI*DM,
                                          xz16, 2*DI, DM, 2*DI, 0, 0, 0, nullptr, 1); }

        conv_silu_kernel<<<(TOK*DI + 255)/256, 256>>>(
            xz16, convw + (size_t)layer*DI*4, convb + (size_t)layer*DI, xc16);

        // x_dbl partials: N=80, K=1536, split-K=16 -> 16 fp32 partial buffers
        { dim3 g(TOK/128, 1, XSPLIT);
          gemm_mma<<<g, 256, GEMM_SMEM>>>(xc16, DI, wxp16 + (size_t)layer*XD*DI,
                                          xdp, XD, DI, XD, 2, TOK*XD, 0, nullptr, 0); }
        sumxd_kernel<<<(TOK*XD + 255)/256, 256>>>(xdp, xd, xd16);

        // dt16 = fp16(softplus(x_dbl[:, :48] @ dt_proj^T + dtb)) : K padded 64
        { dim3 g(TOK/128, DI/128, 1);
          gemm_mma<<<g, 256, GEMM_SMEM>>>(xd16, DTK, wdt16 + (size_t)layer*DI*DTK,
                                          dt16, DI, DTK, DI, 0, 0, 1,
                                          dtb + (size_t)layer*DI, 1); }

        // chunked selective scan (register-state)
        scanA_kernel<<<(BB*CH*DI)/256, 256>>>(xc16, dt16, xd,
                                              Alog + (size_t)layer*DI*DS, Pv, Sv);
        scanB_kernel<<<(BB*DI*DS + 255)/256, 256>>>(Pv, Sv, hin);
        scanC_kernel<<<(BB*CH*DI)/256, 256>>>(xc16, dt16, xd, xz16,
                                              Alog + (size_t)layer*DI*DS,
                                              Dvec + (size_t)layer*DI, hin, y16);

        // out_proj partials: N=768, K=1536, split-K=3 -> hp0/hp1/hp2 (contiguous)
        { dim3 g(TOK/128, DM/128, OSPLIT);
          gemm_mma<<<g, 256, GEMM_SMEM>>>(y16, DI, wout16 + (size_t)layer*DM*DI,
                                          hp0, DM, DI, DM, 2, TOK*DM, 0, nullptr, 0); }
    }

    addnorm_kernel<<<TOK, 256>>>(hp0, hp1, hp2, res, normf, hs16);

    // logits = hs16[:, :384] @ emb^T : N=32000, K=384 (A stride = DM)
    { dim3 g(TOK/128, VOCAB_N/128, 1);
      gemm_mma<<<g, 256, GEMM_SMEM>>>(hs16, DM, wemb16, logits, VOCAB_N, DE, VOCAB_N,
                                      0, 0, 0, nullptr, 0); }
}